// round 1
// baseline (speedup 1.0000x reference)
#include <cuda_runtime.h>
#include <math.h>

#define NB 4
#define CIN 1024
#define CMID 512
#define NPIX 4096
#define MTOT (NB*NPIX)      /* 16384 */
#define KTOT 9216
#define NANCH 36864
#define PRE_TOPN 6000
#define POST_TOPN 300
#define SEL_CAP 16384
#define NBUCKET 65536
#define NEGF (-1.0e10f)

static __device__ float g_wt[KTOT*CMID];
static __device__ float g_feat[MTOT*CMID];
static __device__ float g_boxes[NB*NANCH*4];
static __device__ unsigned g_sbits[NB*NANCH];
static __device__ int g_hist[NB*NBUCKET];
static __device__ int g_thr[NB];
static __device__ int g_cnt[NB];
static __device__ unsigned long long g_sel[NB*SEL_CAP];

// base anchor widths/heights for (ratio 0.5,1,2) x (scale 8,16,32), centers all at 7.5
__constant__ float c_wa[9] = {184.f,368.f,736.f,128.f,256.f,512.f, 88.f,176.f,352.f};
__constant__ float c_ha[9] = { 96.f,192.f,384.f,128.f,256.f,512.f,176.f,352.f,704.f};

// ---------------------------------------------------------------------------
// Weight transpose: OIHW conv_w[n][c*9+r] -> g_wt[(r*1024+c)*512 + n]
// ---------------------------------------------------------------------------
__global__ void transpose_w_kernel(const float* __restrict__ w){
    int i = blockIdx.x*256 + threadIdx.x;
    if (i >= KTOT*CMID) return;
    int n  = i & 511;
    int kp = i >> 9;
    int r  = kp >> 10;
    int c  = kp & 1023;
    g_wt[i] = w[n*KTOT + c*9 + r];
}

__global__ void init_kernel(){
    int i = blockIdx.x*256 + threadIdx.x;
    if (i < NB*NBUCKET) g_hist[i] = 0;
    if (i < NB*SEL_CAP) g_sel[i] = 0ULL;
    if (i < NB)         g_cnt[i] = 0;
}

// ---------------------------------------------------------------------------
// 3x3 conv + bias + relu as implicit GEMM.
// M=16384 pixels (b,y,x), N=512 out channels, K=9216 with k' = r*1024 + c.
// A[m][k'] = X[b, c, y+ky-1, x+kx-1] (zero pad), B[k'][n] = g_wt.
// 128x128 tile, BK=8, 256 threads, 8x8 per thread, smem double buffered.
// ---------------------------------------------------------------------------
__global__ void __launch_bounds__(256,2)
conv3x3_kernel(const float* __restrict__ X, const float* __restrict__ bias){
    __shared__ float As[2][8][128];
    __shared__ float Bs[2][8][128];
    const int tid = threadIdx.x;
    const int n0 = blockIdx.x * 128;
    const int m0 = blockIdx.y * 128;

    // A-tile loader: thread loads 4 consecutive-c values for one pixel
    const int a_m = tid & 127;
    const int a_k = (tid >> 7) << 2;   // 0 or 4
    const int am  = m0 + a_m;
    const int bb  = am >> 12;
    const int yx  = am & 4095;
    const int py  = yx >> 6;
    const int px  = yx & 63;
    const float* Xb = X + (size_t)bb * (CIN*NPIX);

    // B-tile loader: thread loads 4 k-rows for one n (coalesced over n)
    const int w_n = tid & 127;
    const int w_k = (tid >> 7) << 2;

    // compute micro-tile position
    const int tm = (tid >> 4) << 2;    // 0..60
    const int tn = (tid & 15) << 2;    // 0..60

    float acc[8][8];
#pragma unroll
    for (int i=0;i<8;i++)
#pragma unroll
        for (int j=0;j<8;j++) acc[i][j]=0.f;

    float ar[4], br[4];
    { // prologue, ktile 0: r=0 -> (ky,kx)=(-1,-1)
        const int oy = py - 1, ox = px - 1;
        const bool ok = ((unsigned)oy < 64u) && ((unsigned)ox < 64u);
        const float* ap = Xb + (a_k*4096 + oy*64 + ox);
#pragma unroll
        for (int i=0;i<4;i++) ar[i] = ok ? ap[i*4096] : 0.f;
        const float* wp = g_wt + (size_t)w_k*512 + n0 + w_n;
#pragma unroll
        for (int i=0;i<4;i++) br[i] = wp[i*512];
#pragma unroll
        for (int i=0;i<4;i++) As[0][a_k+i][a_m] = ar[i];
#pragma unroll
        for (int i=0;i<4;i++) Bs[0][w_k+i][w_n] = br[i];
    }
    __syncthreads();

    int buf = 0;
    const int NKT = KTOT/8;   // 1152
    for (int kt = 0; kt < NKT; ++kt) {
        if (kt + 1 < NKT) {
            const int kb = (kt+1) << 3;
            const int r  = kb >> 10;          // 0..8
            const int cb = kb & 1023;
            const int ky = r/3, kx = r - ky*3;
            const int oy = py + ky - 1, ox = px + kx - 1;
            const bool ok = ((unsigned)oy < 64u) && ((unsigned)ox < 64u);
            const float* ap = Xb + ((cb + a_k)*4096 + oy*64 + ox);
#pragma unroll
            for (int i=0;i<4;i++) ar[i] = ok ? ap[i*4096] : 0.f;
            const float* wp = g_wt + (size_t)(kb + w_k)*512 + n0 + w_n;
#pragma unroll
            for (int i=0;i<4;i++) br[i] = wp[i*512];
        }
#pragma unroll
        for (int kk=0;kk<8;kk++){
            float a[8], b[8];
            float4 t0 = *(const float4*)&As[buf][kk][tm];
            float4 t1 = *(const float4*)&As[buf][kk][64+tm];
            float4 u0 = *(const float4*)&Bs[buf][kk][tn];
            float4 u1 = *(const float4*)&Bs[buf][kk][64+tn];
            a[0]=t0.x;a[1]=t0.y;a[2]=t0.z;a[3]=t0.w;
            a[4]=t1.x;a[5]=t1.y;a[6]=t1.z;a[7]=t1.w;
            b[0]=u0.x;b[1]=u0.y;b[2]=u0.z;b[3]=u0.w;
            b[4]=u1.x;b[5]=u1.y;b[6]=u1.z;b[7]=u1.w;
#pragma unroll
            for (int i=0;i<8;i++)
#pragma unroll
                for (int j=0;j<8;j++) acc[i][j] += a[i]*b[j];
        }
        if (kt + 1 < NKT) {
            const int nb2 = buf^1;
#pragma unroll
            for (int i=0;i<4;i++) As[nb2][a_k+i][a_m] = ar[i];
#pragma unroll
            for (int i=0;i<4;i++) Bs[nb2][w_k+i][w_n] = br[i];
        }
        __syncthreads();
        buf ^= 1;
    }

#pragma unroll
    for (int i=0;i<8;i++){
        const int mr = m0 + ((i<4)? (tm+i) : (64+tm+i-4));
        float* op = g_feat + (size_t)mr*CMID + n0;
#pragma unroll
        for (int j=0;j<8;j++){
            const int nc = (j<4)? (tn+j) : (64+tn+j-4);
            float v = acc[i][j] + bias[n0+nc];
            op[nc] = v > 0.f ? v : 0.f;
        }
    }
}

// ---------------------------------------------------------------------------
// 1x1 heads (18 cls + 36 bbox) + softmax + anchor decode + clip + histogram.
// One warp per pixel; 54x512 weights cached in dynamic smem.
// ---------------------------------------------------------------------------
__global__ void __launch_bounds__(512)
head_kernel(const float* __restrict__ cls_w, const float* __restrict__ cls_b,
            const float* __restrict__ bbox_w, const float* __restrict__ bbox_b,
            const float* __restrict__ im_info){
    extern __shared__ float ws[];            // 54*512 floats
    __shared__ float bs[54];
    const int tid = threadIdx.x;
    for (int i = tid; i < 18*512; i += 512) ws[i] = cls_w[i];
    for (int i = tid; i < 36*512; i += 512) ws[18*512 + i] = bbox_w[i];
    if (tid < 18) bs[tid] = cls_b[tid];
    else if (tid < 54) bs[tid] = bbox_b[tid-18];
    __syncthreads();

    const int lane = tid & 31;
    const int warp = tid >> 5;
    const int gw = blockIdx.x*16 + warp;
    const int nw = gridDim.x*16;
    for (int m = gw; m < MTOT; m += nw) {
        const float* f = g_feat + (size_t)m*CMID;
        float fr[16];
#pragma unroll
        for (int j=0;j<16;j++) fr[j] = f[lane + 32*j];
        float o[54];
#pragma unroll
        for (int t=0;t<54;t++){
            const float* wr = ws + t*512;
            float s = 0.f;
#pragma unroll
            for (int j=0;j<16;j++) s += fr[j]*wr[lane+32*j];
#pragma unroll
            for (int d=16; d>0; d>>=1) s += __shfl_xor_sync(0xffffffffu, s, d);
            o[t] = s + bs[t];
        }
        if (lane < 9) {
            const int a  = lane;
            const int b  = m >> 12;
            const int yx = m & 4095;
            const int py = yx >> 6, px = yx & 63;
            float c0 = o[a], c1 = o[9+a];
            float mx = fmaxf(c0,c1);
            float e0 = expf(c0-mx), e1 = expf(c1-mx);
            float sc = e1/(e0+e1);
            float dx = o[18+a*4+0], dy = o[18+a*4+1];
            float dw = o[18+a*4+2], dh = o[18+a*4+3];
            float wa = c_wa[a], ha = c_ha[a];
            float cxa = 7.5f + 16.f*(float)px;
            float cya = 7.5f + 16.f*(float)py;
            float cx = dx*wa + cxa;
            float cy = dy*ha + cya;
            float pw = expf(dw)*wa;
            float ph = expf(dh)*ha;
            float imh = im_info[b*3+0], imw = im_info[b*3+1];
            float x1 = fminf(fmaxf(cx - 0.5f*pw, 0.f), imw - 1.f);
            float y1 = fminf(fmaxf(cy - 0.5f*ph, 0.f), imh - 1.f);
            float x2 = fminf(fmaxf(cx + 0.5f*pw, 0.f), imw - 1.f);
            float y2 = fminf(fmaxf(cy + 0.5f*ph, 0.f), imh - 1.f);
            const int idx = yx*9 + a;
            float* bp = g_boxes + ((size_t)b*NANCH + idx)*4;
            bp[0]=x1; bp[1]=y1; bp[2]=x2; bp[3]=y2;
            unsigned bits = __float_as_uint(sc);   // sc in (0,1): bits monotone
            g_sbits[b*NANCH + idx] = bits;
            atomicAdd(&g_hist[b*NBUCKET + (bits>>16)], 1);
        }
    }
}

// ---------------------------------------------------------------------------
// Per-image threshold bucket: smallest T with count(bucket >= T) >= 6000.
// ---------------------------------------------------------------------------
__global__ void __launch_bounds__(1024) thresh_kernel(){
    __shared__ int csum[1024];
    const int b = blockIdx.x;
    const int t = threadIdx.x;
    const int* h = g_hist + b*NBUCKET;
    const int base = t*64;
    int s = 0;
    for (int i=0;i<64;i++) s += h[base+i];
    csum[t] = s;
    __syncthreads();
    for (int d=1; d<1024; d<<=1){               // suffix scan (Hillis-Steele)
        int add = (t+d < 1024) ? csum[t+d] : 0;
        __syncthreads();
        csum[t] += add;
        __syncthreads();
    }
    int St = csum[t];
    int Sn = (t+1 < 1024) ? csum[t+1] : 0;
    if (St >= PRE_TOPN && Sn < PRE_TOPN){
        int acc = Sn;
        int T = base;
        for (int i=63;i>=0;i--){
            acc += h[base+i];
            if (acc >= PRE_TOPN){ T = base+i; break; }
        }
        g_thr[b] = T;
    }
}

__global__ void compact_kernel(){
    int i = blockIdx.x*256 + threadIdx.x;
    if (i >= NB*NANCH) return;
    int b = i / NANCH;
    int idx = i - b*NANCH;
    unsigned bits = g_sbits[i];
    if ((int)(bits >> 16) >= g_thr[b]){
        int p = atomicAdd(&g_cnt[b], 1);
        if (p < SEL_CAP)
            // key: score bits high, ~idx low -> descending sort gives
            // (score desc, index asc) exactly like jax.lax.top_k
            g_sel[b*SEL_CAP + p] = ((unsigned long long)bits << 32) | (unsigned)(~idx);
    }
}

// ---------------------------------------------------------------------------
// In-smem bitonic sort of 16384 packed keys per image (descending).
// ---------------------------------------------------------------------------
__global__ void __launch_bounds__(1024) sort_kernel(){
    extern __shared__ unsigned long long sh[];
    const int b = blockIdx.x;
    unsigned long long* gs = g_sel + b*SEL_CAP;
    for (int i=threadIdx.x;i<SEL_CAP;i+=1024) sh[i] = gs[i];
    __syncthreads();
    for (int k=2;k<=SEL_CAP;k<<=1){
        for (int j=k>>1;j>0;j>>=1){
            for (int t=threadIdx.x;t<SEL_CAP/2;t+=1024){
                int i  = 2*t - (t & (j-1));
                int ix = i + j;
                unsigned long long a = sh[i], c = sh[ix];
                bool dir = ((i & k) == 0);        // descending overall
                bool sw  = dir ? (a < c) : (a > c);
                if (sw){ sh[i]=c; sh[ix]=a; }
            }
            __syncthreads();
        }
    }
    for (int i=threadIdx.x;i<SEL_CAP;i+=1024) gs[i]=sh[i];
}

// ---------------------------------------------------------------------------
// Greedy NMS on sorted top-6000. Since scores are sorted descending,
// argmax(live) == first unsuppressed index (tie-break matches jnp.argmax).
// ---------------------------------------------------------------------------
__global__ void __launch_bounds__(1024) nms_kernel(float* __restrict__ out){
    extern __shared__ float sm[];
    float* X1 = sm;
    float* Y1 = X1 + PRE_TOPN;
    float* X2 = Y1 + PRE_TOPN;
    float* Y2 = X2 + PRE_TOPN;
    float* AR = Y2 + PRE_TOPN;
    float* SC = AR + PRE_TOPN;
    __shared__ int   s_pick;
    __shared__ float s_box[5];
    const int b = blockIdx.x;
    const unsigned long long* keys = g_sel + b*SEL_CAP;
    for (int i=threadIdx.x;i<PRE_TOPN;i+=1024){
        unsigned long long kv = keys[i];
        unsigned idx = ~(unsigned)(kv & 0xFFFFFFFFull);
        float sc = __uint_as_float((unsigned)(kv >> 32));
        const float* bp = g_boxes + ((size_t)b*NANCH + idx)*4;
        float x1=bp[0], y1=bp[1], x2=bp[2], y2=bp[3];
        X1[i]=x1; Y1[i]=y1; X2[i]=x2; Y2[i]=y2;
        AR[i]=(x2-x1+1.f)*(y2-y1+1.f);
        SC[i]=sc;
    }
    __syncthreads();
    int p = 0;   // only thread 0 uses it
    for (int it=0; it<POST_TOPN; ++it){
        if (threadIdx.x == 0){
            while (p < PRE_TOPN && SC[p] == NEGF) p++;
            if (p < PRE_TOPN){
                s_pick = p;
                s_box[0]=X1[p]; s_box[1]=Y1[p]; s_box[2]=X2[p]; s_box[3]=Y2[p]; s_box[4]=AR[p];
                float* r = out + (size_t)(b*POST_TOPN + it)*5;
                r[0]=(float)b; r[1]=X1[p]; r[2]=Y1[p]; r[3]=X2[p]; r[4]=Y2[p];
                out[NB*POST_TOPN*5 + b*POST_TOPN + it] = SC[p];
            } else {
                s_pick = -1;
                float* r = out + (size_t)(b*POST_TOPN + it)*5;
                r[0]=0.f; r[1]=0.f; r[2]=0.f; r[3]=0.f; r[4]=0.f;
                out[NB*POST_TOPN*5 + b*POST_TOPN + it] = 0.f;
            }
        }
        __syncthreads();
        if (s_pick >= 0){
            float bx1=s_box[0], by1=s_box[1], bx2=s_box[2], by2=s_box[3], ba=s_box[4];
            for (int i=threadIdx.x;i<PRE_TOPN;i+=1024){
                float sc = SC[i];
                if (sc == NEGF) continue;
                float xx1 = fmaxf(bx1, X1[i]);
                float yy1 = fmaxf(by1, Y1[i]);
                float xx2 = fminf(bx2, X2[i]);
                float yy2 = fminf(by2, Y2[i]);
                float iw = fmaxf(xx2-xx1+1.f, 0.f);
                float ih = fmaxf(yy2-yy1+1.f, 0.f);
                float inter = iw*ih;
                float iou = inter/(ba + AR[i] - inter);
                if (iou > 0.7f) SC[i] = NEGF;   // suppresses the pick itself too (iou=1)
            }
        }
        __syncthreads();
    }
}

// ---------------------------------------------------------------------------
extern "C" void kernel_launch(void* const* d_in, const int* in_sizes, int n_in,
                              void* d_out, int out_size) {
    (void)in_sizes; (void)n_in; (void)out_size;
    const float* base_feat = (const float*)d_in[0];
    const float* im_info   = (const float*)d_in[1];
    const float* conv_w    = (const float*)d_in[4];
    const float* conv_b    = (const float*)d_in[5];
    const float* cls_w     = (const float*)d_in[6];
    const float* cls_b     = (const float*)d_in[7];
    const float* bbox_w    = (const float*)d_in[8];
    const float* bbox_b    = (const float*)d_in[9];
    float* out = (float*)d_out;

    cudaFuncSetAttribute(head_kernel, cudaFuncAttributeMaxDynamicSharedMemorySize, 54*512*4);
    cudaFuncSetAttribute(sort_kernel, cudaFuncAttributeMaxDynamicSharedMemorySize, SEL_CAP*8);
    cudaFuncSetAttribute(nms_kernel,  cudaFuncAttributeMaxDynamicSharedMemorySize, PRE_TOPN*6*4);

    transpose_w_kernel<<<(KTOT*CMID + 255)/256, 256>>>(conv_w);
    init_kernel<<<(NB*NBUCKET + 255)/256, 256>>>();
    conv3x3_kernel<<<dim3(4,128), 256>>>(base_feat, conv_b);
    head_kernel<<<148, 512, 54*512*4>>>(cls_w, cls_b, bbox_w, bbox_b, im_info);
    thresh_kernel<<<NB, 1024>>>();
    compact_kernel<<<(NB*NANCH + 255)/256, 256>>>();
    sort_kernel<<<NB, 1024, SEL_CAP*8>>>();
    nms_kernel<<<NB, 1024, PRE_TOPN*6*4>>>(out);
}

// round 5
// speedup vs baseline: 1.0754x; 1.0754x over previous
#include <cuda_runtime.h>
#include <math.h>

#define NB 4
#define CIN 1024
#define CMID 512
#define NPIX 4096
#define MTOT (NB*NPIX)      /* 16384 */
#define KTOT 9216
#define NANCH 36864
#define PRE_TOPN 6000
#define POST_TOPN 300
#define SEL_CAP 16384
#define NBUCKET 65536
#define NEGF (-1.0e10f)

static __device__ float g_wt[KTOT*CMID];
static __device__ float g_feat[(size_t)MTOT*CMID];
static __device__ float g_boxes[NB*NANCH*4];
static __device__ unsigned g_sbits[NB*NANCH];
static __device__ int g_hist[NB*NBUCKET];
static __device__ int g_thr[NB];
static __device__ int g_cnt[NB];
static __device__ unsigned long long g_sel[NB*SEL_CAP];

// base anchor widths/heights for (ratio 0.5,1,2) x (scale 8,16,32), centers all at 7.5
__constant__ float c_wa[9] = {184.f,368.f,736.f,128.f,256.f,512.f, 88.f,176.f,352.f};
__constant__ float c_ha[9] = { 96.f,192.f,384.f,128.f,256.f,512.f,176.f,352.f,704.f};

// ---- packed f32x2 helpers (Blackwell) --------------------------------------
__device__ __forceinline__ unsigned long long pk2(float x, float y){
    unsigned long long r;
    asm("mov.b64 %0, {%1,%2};" : "=l"(r) : "f"(x), "f"(y));
    return r;
}
__device__ __forceinline__ void upk2(unsigned long long v, float& x, float& y){
    asm("mov.b64 {%0,%1}, %2;" : "=f"(x), "=f"(y) : "l"(v));
}
__device__ __forceinline__ void fma2(unsigned long long& d, unsigned long long a, unsigned long long b){
    asm("fma.rn.f32x2 %0, %1, %2, %0;" : "+l"(d) : "l"(a), "l"(b));
}

// ---------------------------------------------------------------------------
// Weight transpose: OIHW conv_w[n][c*9+r] -> g_wt[(r*1024+c)*512 + n]
// ---------------------------------------------------------------------------
__global__ void transpose_w_kernel(const float* __restrict__ w){
    int i = blockIdx.x*256 + threadIdx.x;
    if (i >= KTOT*CMID) return;
    int n  = i & 511;
    int kp = i >> 9;
    int r  = kp >> 10;
    int c  = kp & 1023;
    g_wt[i] = w[n*KTOT + c*9 + r];
}

__global__ void init_kernel(){
    int i = blockIdx.x*256 + threadIdx.x;
    if (i < NB*NBUCKET) g_hist[i] = 0;
    if (i < NB*SEL_CAP) g_sel[i] = 0ULL;
    if (i < NB)         g_cnt[i] = 0;
}

// ---------------------------------------------------------------------------
// 3x3 conv + bias + relu as implicit GEMM (fp32, packed f32x2 FMA).
// Identical arithmetic (operands, rounding, k-order) to the proven scalar
// version — each lane of fma.rn.f32x2 is an independent rn FMA.
// ---------------------------------------------------------------------------
__global__ void __launch_bounds__(256,2)
conv3x3_kernel(const float* __restrict__ X, const float* __restrict__ bias){
    __shared__ float As[2][8][128];
    __shared__ float Bs[2][8][128];
    const int tid = threadIdx.x;
    const int n0 = blockIdx.x * 128;
    const int m0 = blockIdx.y * 128;

    const int a_m = tid & 127;
    const int a_k = (tid >> 7) << 2;   // 0 or 4
    const int am  = m0 + a_m;
    const int bb  = am >> 12;
    const int yx  = am & 4095;
    const int py  = yx >> 6;
    const int px  = yx & 63;
    const float* Xb = X + (size_t)bb * (CIN*NPIX);

    const int w_n = tid & 127;
    const int w_k = (tid >> 7) << 2;

    const int tm = (tid >> 4) << 2;    // 0..60
    const int tn = (tid & 15) << 2;    // 0..60

    // acc2[i][jh] = packed pair (acc[i][2jh], acc[i][2jh+1])
    unsigned long long acc2[8][4];
    const unsigned long long z2 = pk2(0.f, 0.f);
#pragma unroll
    for (int i=0;i<8;i++)
#pragma unroll
        for (int jh=0;jh<4;jh++) acc2[i][jh] = z2;

    float ar[4], br[4];
    { // prologue, ktile 0: r=0 -> (ky,kx)=(-1,-1)
        const int oy = py - 1, ox = px - 1;
        const bool ok = ((unsigned)oy < 64u) && ((unsigned)ox < 64u);
        const float* ap = Xb + (a_k*4096 + oy*64 + ox);
#pragma unroll
        for (int i=0;i<4;i++) ar[i] = ok ? ap[i*4096] : 0.f;
        const float* wp = g_wt + (size_t)w_k*512 + n0 + w_n;
#pragma unroll
        for (int i=0;i<4;i++) br[i] = wp[i*512];
#pragma unroll
        for (int i=0;i<4;i++) As[0][a_k+i][a_m] = ar[i];
#pragma unroll
        for (int i=0;i<4;i++) Bs[0][w_k+i][w_n] = br[i];
    }
    __syncthreads();

    int buf = 0;
    const int NKT = KTOT/8;   // 1152
    for (int kt = 0; kt < NKT; ++kt) {
        if (kt + 1 < NKT) {
            const int kb = (kt+1) << 3;
            const int r  = kb >> 10;          // 0..8
            const int cb = kb & 1023;
            const int ky = r/3, kx = r - ky*3;
            const int oy = py + ky - 1, ox = px + kx - 1;
            const bool ok = ((unsigned)oy < 64u) && ((unsigned)ox < 64u);
            const float* ap = Xb + ((cb + a_k)*4096 + oy*64 + ox);
#pragma unroll
            for (int i=0;i<4;i++) ar[i] = ok ? ap[i*4096] : 0.f;
            const float* wp = g_wt + (size_t)(kb + w_k)*512 + n0 + w_n;
#pragma unroll
            for (int i=0;i<4;i++) br[i] = wp[i*512];
        }
#pragma unroll
        for (int kk=0;kk<8;kk++){
            float a[8];
            float4 t0 = *(const float4*)&As[buf][kk][tm];
            float4 t1 = *(const float4*)&As[buf][kk][64+tm];
            float4 u0 = *(const float4*)&Bs[buf][kk][tn];
            float4 u1 = *(const float4*)&Bs[buf][kk][64+tn];
            a[0]=t0.x;a[1]=t0.y;a[2]=t0.z;a[3]=t0.w;
            a[4]=t1.x;a[5]=t1.y;a[6]=t1.z;a[7]=t1.w;
            unsigned long long bp[4];
            bp[0]=pk2(u0.x,u0.y); bp[1]=pk2(u0.z,u0.w);
            bp[2]=pk2(u1.x,u1.y); bp[3]=pk2(u1.z,u1.w);
#pragma unroll
            for (int i=0;i<8;i++){
                unsigned long long ap2 = pk2(a[i], a[i]);
#pragma unroll
                for (int jh=0;jh<4;jh++) fma2(acc2[i][jh], ap2, bp[jh]);
            }
        }
        if (kt + 1 < NKT) {
            const int nb2 = buf^1;
#pragma unroll
            for (int i=0;i<4;i++) As[nb2][a_k+i][a_m] = ar[i];
#pragma unroll
            for (int i=0;i<4;i++) Bs[nb2][w_k+i][w_n] = br[i];
        }
        __syncthreads();
        buf ^= 1;
    }

#pragma unroll
    for (int i=0;i<8;i++){
        const int mr = m0 + ((i<4)? (tm+i) : (64+tm+i-4));
        float* op = g_feat + (size_t)mr*CMID + n0;
#pragma unroll
        for (int jh=0;jh<4;jh++){
            float v0, v1;
            upk2(acc2[i][jh], v0, v1);
            const int j0 = 2*jh, j1 = 2*jh+1;
            const int nc0 = (j0<4)? (tn+j0) : (64+tn+j0-4);
            const int nc1 = (j1<4)? (tn+j1) : (64+tn+j1-4);
            float w0 = v0 + bias[n0+nc0];
            float w1 = v1 + bias[n0+nc1];
            op[nc0] = w0 > 0.f ? w0 : 0.f;
            op[nc1] = w1 > 0.f ? w1 : 0.f;
        }
    }
}

// ---------------------------------------------------------------------------
// 1x1 heads (18 cls + 36 bbox) + softmax + anchor decode + clip + histogram.
// ---------------------------------------------------------------------------
__global__ void __launch_bounds__(512)
head_kernel(const float* __restrict__ cls_w, const float* __restrict__ cls_b,
            const float* __restrict__ bbox_w, const float* __restrict__ bbox_b,
            const float* __restrict__ im_info){
    extern __shared__ float ws[];            // 54*512 floats
    __shared__ float bs[54];
    const int tid = threadIdx.x;
    for (int i = tid; i < 18*512; i += 512) ws[i] = cls_w[i];
    for (int i = tid; i < 36*512; i += 512) ws[18*512 + i] = bbox_w[i];
    if (tid < 18) bs[tid] = cls_b[tid];
    else if (tid < 54) bs[tid] = bbox_b[tid-18];
    __syncthreads();

    const int lane = tid & 31;
    const int warp = tid >> 5;
    const int gw = blockIdx.x*16 + warp;
    const int nw = gridDim.x*16;
    for (int m = gw; m < MTOT; m += nw) {
        const float* f = g_feat + (size_t)m*CMID;
        float fr[16];
#pragma unroll
        for (int j=0;j<16;j++) fr[j] = f[lane + 32*j];
        float o[54];
#pragma unroll
        for (int t=0;t<54;t++){
            const float* wr = ws + t*512;
            float s = 0.f;
#pragma unroll
            for (int j=0;j<16;j++) s += fr[j]*wr[lane+32*j];
#pragma unroll
            for (int d=16; d>0; d>>=1) s += __shfl_xor_sync(0xffffffffu, s, d);
            o[t] = s + bs[t];
        }
        if (lane < 9) {
            const int a  = lane;
            const int b  = m >> 12;
            const int yx = m & 4095;
            const int py = yx >> 6, px = yx & 63;
            float c0 = o[a], c1 = o[9+a];
            float mx = fmaxf(c0,c1);
            float e0 = expf(c0-mx), e1 = expf(c1-mx);
            float sc = e1/(e0+e1);
            float dx = o[18+a*4+0], dy = o[18+a*4+1];
            float dw = o[18+a*4+2], dh = o[18+a*4+3];
            float wa = c_wa[a], ha = c_ha[a];
            float cxa = 7.5f + 16.f*(float)px;
            float cya = 7.5f + 16.f*(float)py;
            float cx = dx*wa + cxa;
            float cy = dy*ha + cya;
            float pw = expf(dw)*wa;
            float ph = expf(dh)*ha;
            float imh = im_info[b*3+0], imw = im_info[b*3+1];
            float x1 = fminf(fmaxf(cx - 0.5f*pw, 0.f), imw - 1.f);
            float y1 = fminf(fmaxf(cy - 0.5f*ph, 0.f), imh - 1.f);
            float x2 = fminf(fmaxf(cx + 0.5f*pw, 0.f), imw - 1.f);
            float y2 = fminf(fmaxf(cy + 0.5f*ph, 0.f), imh - 1.f);
            const int idx = yx*9 + a;
            float* bp = g_boxes + ((size_t)b*NANCH + idx)*4;
            bp[0]=x1; bp[1]=y1; bp[2]=x2; bp[3]=y2;
            unsigned bits = __float_as_uint(sc);   // sc in (0,1): bits monotone
            g_sbits[b*NANCH + idx] = bits;
            atomicAdd(&g_hist[b*NBUCKET + (bits>>16)], 1);
        }
    }
}

// ---------------------------------------------------------------------------
// Per-image threshold bucket: smallest T with count(bucket >= T) >= 6000.
// ---------------------------------------------------------------------------
__global__ void __launch_bounds__(1024) thresh_kernel(){
    __shared__ int csum[1024];
    const int b = blockIdx.x;
    const int t = threadIdx.x;
    const int* h = g_hist + b*NBUCKET;
    const int base = t*64;
    int s = 0;
    for (int i=0;i<64;i++) s += h[base+i];
    csum[t] = s;
    __syncthreads();
    for (int d=1; d<1024; d<<=1){               // suffix scan
        int add = (t+d < 1024) ? csum[t+d] : 0;
        __syncthreads();
        csum[t] += add;
        __syncthreads();
    }
    int St = csum[t];
    int Sn = (t+1 < 1024) ? csum[t+1] : 0;
    if (St >= PRE_TOPN && Sn < PRE_TOPN){
        int acc = Sn;
        int T = base;
        for (int i=63;i>=0;i--){
            acc += h[base+i];
            if (acc >= PRE_TOPN){ T = base+i; break; }
        }
        g_thr[b] = T;
    }
}

__global__ void compact_kernel(){
    int i = blockIdx.x*256 + threadIdx.x;
    if (i >= NB*NANCH) return;
    int b = i / NANCH;
    int idx = i - b*NANCH;
    unsigned bits = g_sbits[i];
    if ((int)(bits >> 16) >= g_thr[b]){
        int p = atomicAdd(&g_cnt[b], 1);
        if (p < SEL_CAP)
            g_sel[b*SEL_CAP + p] = ((unsigned long long)bits << 32) | (unsigned)(~idx);
    }
}

// ---------------------------------------------------------------------------
// In-smem bitonic sort of 16384 packed keys per image (descending).
// ---------------------------------------------------------------------------
__global__ void __launch_bounds__(1024) sort_kernel(){
    extern __shared__ unsigned long long sh[];
    const int b = blockIdx.x;
    unsigned long long* gs = g_sel + b*SEL_CAP;
    for (int i=threadIdx.x;i<SEL_CAP;i+=1024) sh[i] = gs[i];
    __syncthreads();
    for (int k=2;k<=SEL_CAP;k<<=1){
        for (int j=k>>1;j>0;j>>=1){
            for (int t=threadIdx.x;t<SEL_CAP/2;t+=1024){
                int i  = 2*t - (t & (j-1));
                int ix = i + j;
                unsigned long long a = sh[i], c = sh[ix];
                bool dir = ((i & k) == 0);        // descending overall
                bool sw  = dir ? (a < c) : (a > c);
                if (sw){ sh[i]=c; sh[ix]=a; }
            }
            __syncthreads();
        }
    }
    for (int i=threadIdx.x;i<SEL_CAP;i+=1024) gs[i]=sh[i];
}

// ---------------------------------------------------------------------------
// Greedy NMS on sorted top-6000.
// ---------------------------------------------------------------------------
__global__ void __launch_bounds__(1024) nms_kernel(float* __restrict__ out){
    extern __shared__ float sm[];
    float* X1 = sm;
    float* Y1 = X1 + PRE_TOPN;
    float* X2 = Y1 + PRE_TOPN;
    float* Y2 = X2 + PRE_TOPN;
    float* AR = Y2 + PRE_TOPN;
    float* SC = AR + PRE_TOPN;
    __shared__ int   s_pick;
    __shared__ float s_box[5];
    const int b = blockIdx.x;
    const unsigned long long* keys = g_sel + b*SEL_CAP;
    for (int i=threadIdx.x;i<PRE_TOPN;i+=1024){
        unsigned long long kv = keys[i];
        unsigned idx = ~(unsigned)(kv & 0xFFFFFFFFull);
        float sc = __uint_as_float((unsigned)(kv >> 32));
        const float* bp = g_boxes + ((size_t)b*NANCH + idx)*4;
        float x1=bp[0], y1=bp[1], x2=bp[2], y2=bp[3];
        X1[i]=x1; Y1[i]=y1; X2[i]=x2; Y2[i]=y2;
        AR[i]=(x2-x1+1.f)*(y2-y1+1.f);
        SC[i]=sc;
    }
    __syncthreads();
    int p = 0;   // only thread 0 uses it
    for (int it=0; it<POST_TOPN; ++it){
        if (threadIdx.x == 0){
            while (p < PRE_TOPN && SC[p] == NEGF) p++;
            if (p < PRE_TOPN){
                s_pick = p;
                s_box[0]=X1[p]; s_box[1]=Y1[p]; s_box[2]=X2[p]; s_box[3]=Y2[p]; s_box[4]=AR[p];
                float* r = out + (size_t)(b*POST_TOPN + it)*5;
                r[0]=(float)b; r[1]=X1[p]; r[2]=Y1[p]; r[3]=X2[p]; r[4]=Y2[p];
                out[NB*POST_TOPN*5 + b*POST_TOPN + it] = SC[p];
            } else {
                s_pick = -1;
                float* r = out + (size_t)(b*POST_TOPN + it)*5;
                r[0]=0.f; r[1]=0.f; r[2]=0.f; r[3]=0.f; r[4]=0.f;
                out[NB*POST_TOPN*5 + b*POST_TOPN + it] = 0.f;
            }
        }
        __syncthreads();
        if (s_pick >= 0){
            float bx1=s_box[0], by1=s_box[1], bx2=s_box[2], by2=s_box[3], ba=s_box[4];
            for (int i=threadIdx.x;i<PRE_TOPN;i+=1024){
                float sc = SC[i];
                if (sc == NEGF) continue;
                float xx1 = fmaxf(bx1, X1[i]);
                float yy1 = fmaxf(by1, Y1[i]);
                float xx2 = fminf(bx2, X2[i]);
                float yy2 = fminf(by2, Y2[i]);
                float iw = fmaxf(xx2-xx1+1.f, 0.f);
                float ih = fmaxf(yy2-yy1+1.f, 0.f);
                float inter = iw*ih;
                float iou = inter/(ba + AR[i] - inter);
                if (iou > 0.7f) SC[i] = NEGF;
            }
        }
        __syncthreads();
    }
}

// ---------------------------------------------------------------------------
extern "C" void kernel_launch(void* const* d_in, const int* in_sizes, int n_in,
                              void* d_out, int out_size) {
    (void)in_sizes; (void)n_in; (void)out_size;
    const float* base_feat = (const float*)d_in[0];
    const float* im_info   = (const float*)d_in[1];
    const float* conv_w    = (const float*)d_in[4];
    const float* conv_b    = (const float*)d_in[5];
    const float* cls_w     = (const float*)d_in[6];
    const float* cls_b     = (const float*)d_in[7];
    const float* bbox_w    = (const float*)d_in[8];
    const float* bbox_b    = (const float*)d_in[9];
    float* out = (float*)d_out;

    cudaFuncSetAttribute(head_kernel, cudaFuncAttributeMaxDynamicSharedMemorySize, 54*512*4);
    cudaFuncSetAttribute(sort_kernel, cudaFuncAttributeMaxDynamicSharedMemorySize, SEL_CAP*8);
    cudaFuncSetAttribute(nms_kernel,  cudaFuncAttributeMaxDynamicSharedMemorySize, PRE_TOPN*6*4);

    transpose_w_kernel<<<(KTOT*CMID + 255)/256, 256>>>(conv_w);
    init_kernel<<<(NB*NBUCKET + 255)/256, 256>>>();
    conv3x3_kernel<<<dim3(4,128), 256>>>(base_feat, conv_b);
    head_kernel<<<148, 512, 54*512*4>>>(cls_w, cls_b, bbox_w, bbox_b, im_info);
    thresh_kernel<<<NB, 1024>>>();
    compact_kernel<<<(NB*NANCH + 255)/256, 256>>>();
    sort_kernel<<<NB, 1024, SEL_CAP*8>>>();
    nms_kernel<<<NB, 1024, PRE_TOPN*6*4>>>(out);
}

// round 6
// speedup vs baseline: 1.1136x; 1.0356x over previous
#include <cuda_runtime.h>
#include <math.h>

#define NB 4
#define CIN 1024
#define CMID 512
#define NPIX 4096
#define MTOT (NB*NPIX)      /* 16384 */
#define KTOT 9216
#define NANCH 36864
#define PRE_TOPN 6000
#define POST_TOPN 300
#define SEL_CAP 16384
#define NBUCKET 65536
#define NEGF (-1.0e10f)

static __device__ float g_wt[KTOT*CMID];
static __device__ float g_feat[(size_t)MTOT*CMID];
static __device__ float g_boxes[NB*NANCH*4];
static __device__ unsigned g_sbits[NB*NANCH];
static __device__ int g_hist[NB*NBUCKET];
static __device__ int g_thr[NB];
static __device__ int g_cnt[NB];
static __device__ unsigned long long g_sel[NB*SEL_CAP];

// base anchor widths/heights for (ratio 0.5,1,2) x (scale 8,16,32), centers all at 7.5
__constant__ float c_wa[9] = {184.f,368.f,736.f,128.f,256.f,512.f, 88.f,176.f,352.f};
__constant__ float c_ha[9] = { 96.f,192.f,384.f,128.f,256.f,512.f,176.f,352.f,704.f};

// ---- packed f32x2 helpers (Blackwell) --------------------------------------
__device__ __forceinline__ unsigned long long pk2(float x, float y){
    unsigned long long r;
    asm("mov.b64 %0, {%1,%2};" : "=l"(r) : "f"(x), "f"(y));
    return r;
}
__device__ __forceinline__ void upk2(unsigned long long v, float& x, float& y){
    asm("mov.b64 {%0,%1}, %2;" : "=f"(x), "=f"(y) : "l"(v));
}
__device__ __forceinline__ void fma2(unsigned long long& d, unsigned long long a, unsigned long long b){
    asm("fma.rn.f32x2 %0, %1, %2, %0;" : "+l"(d) : "l"(a), "l"(b));
}

// ---------------------------------------------------------------------------
// Weight transpose (coalesced, smem-tiled):
// OIHW conv_w[n][c*9+r] -> g_wt[(r*1024+c)*512 + n]
// Block: 128 n x 8 c x 9 r. Loads contiguous 36-float runs; writes 512B runs.
// ---------------------------------------------------------------------------
__global__ void __launch_bounds__(256)
transpose_w_kernel(const float* __restrict__ w){
    __shared__ float s[128][73];   // [n][(c-c0)*9 + r], pad 73 for bank spread
    const int tid = threadIdx.x;
    const int n0 = blockIdx.y * 128;
    const int c0 = blockIdx.x * 8;
    const int n  = tid >> 1;
    const int half = tid & 1;
    const float* src = w + (size_t)(n0+n)*KTOT + c0*9 + half*36;
#pragma unroll
    for (int i=0;i<36;i++) s[n][half*36 + i] = src[i];
    __syncthreads();
    const int nn = tid & 127;
    const int u  = tid >> 7;
#pragma unroll
    for (int si=0; si<36; ++si){
        int slot = u*36 + si;        // 0..71 = (cc*9 + r)
        int cc = slot / 9, r = slot - cc*9;
        g_wt[(size_t)(r*1024 + c0 + cc)*512 + n0 + nn] = s[nn][slot];
    }
}

__global__ void init_kernel(){
    int i = blockIdx.x*256 + threadIdx.x;
    if (i < NB*NBUCKET) g_hist[i] = 0;
    if (i < NB*SEL_CAP) g_sel[i] = 0ULL;
    if (i < NB)         g_cnt[i] = 0;
}

// ---------------------------------------------------------------------------
// 3x3 conv + bias + relu as implicit GEMM (fp32, packed f32x2 FMA).
// Bit-identical arithmetic to the proven scalar version; inner loop ordered
// (jh outer, i inner) so consecutive FFMA2s share the b operand (.reuse ->
// 2 distinct even-bank regs -> rt2). B loaded as aligned 64-bit from smem.
// ---------------------------------------------------------------------------
__global__ void __launch_bounds__(256,2)
conv3x3_kernel(const float* __restrict__ X, const float* __restrict__ bias){
    __shared__ float As[2][8][128];
    __shared__ float Bs[2][8][128];
    const int tid = threadIdx.x;
    const int n0 = blockIdx.x * 128;
    const int m0 = blockIdx.y * 128;

    const int a_m = tid & 127;
    const int a_k = (tid >> 7) << 2;   // 0 or 4
    const int am  = m0 + a_m;
    const int bb  = am >> 12;
    const int yx  = am & 4095;
    const int py  = yx >> 6;
    const int px  = yx & 63;
    const float* Xb = X + (size_t)bb * (CIN*NPIX);

    const int w_n = tid & 127;
    const int w_k = (tid >> 7) << 2;

    const int tm = (tid >> 4) << 2;    // 0..60
    const int tn = (tid & 15) << 2;    // 0..60

    // acc2[i][jh] = packed pair (acc[i][2jh], acc[i][2jh+1])
    unsigned long long acc2[8][4];
    const unsigned long long z2 = pk2(0.f, 0.f);
#pragma unroll
    for (int i=0;i<8;i++)
#pragma unroll
        for (int jh=0;jh<4;jh++) acc2[i][jh] = z2;

    float ar[4], br[4];
    { // prologue, ktile 0: r=0 -> (ky,kx)=(-1,-1)
        const int oy = py - 1, ox = px - 1;
        const bool ok = ((unsigned)oy < 64u) && ((unsigned)ox < 64u);
        const float* ap = Xb + (a_k*4096 + oy*64 + ox);
#pragma unroll
        for (int i=0;i<4;i++) ar[i] = ok ? ap[i*4096] : 0.f;
        const float* wp = g_wt + (size_t)w_k*512 + n0 + w_n;
#pragma unroll
        for (int i=0;i<4;i++) br[i] = wp[i*512];
#pragma unroll
        for (int i=0;i<4;i++) As[0][a_k+i][a_m] = ar[i];
#pragma unroll
        for (int i=0;i<4;i++) Bs[0][w_k+i][w_n] = br[i];
    }
    __syncthreads();

    int buf = 0;
    const int NKT = KTOT/8;   // 1152
    for (int kt = 0; kt < NKT; ++kt) {
        if (kt + 1 < NKT) {
            const int kb = (kt+1) << 3;
            const int r  = kb >> 10;          // 0..8
            const int cb = kb & 1023;
            const int ky = r/3, kx = r - ky*3;
            const int oy = py + ky - 1, ox = px + kx - 1;
            const bool ok = ((unsigned)oy < 64u) && ((unsigned)ox < 64u);
            const float* ap = Xb + ((cb + a_k)*4096 + oy*64 + ox);
#pragma unroll
            for (int i=0;i<4;i++) ar[i] = ok ? ap[i*4096] : 0.f;
            const float* wp = g_wt + (size_t)(kb + w_k)*512 + n0 + w_n;
#pragma unroll
            for (int i=0;i<4;i++) br[i] = wp[i*512];
        }
#pragma unroll
        for (int kk=0;kk<8;kk++){
            float4 t0 = *(const float4*)&As[buf][kk][tm];
            float4 t1 = *(const float4*)&As[buf][kk][64+tm];
            // B as aligned 64-bit pairs straight from smem (no packing movs)
            const unsigned long long* Bp0 = (const unsigned long long*)&Bs[buf][kk][tn];
            const unsigned long long* Bp1 = (const unsigned long long*)&Bs[buf][kk][64+tn];
            unsigned long long bp[4];
            bp[0]=Bp0[0]; bp[1]=Bp0[1]; bp[2]=Bp1[0]; bp[3]=Bp1[1];
            unsigned long long ap2[8];
            ap2[0]=pk2(t0.x,t0.x); ap2[1]=pk2(t0.y,t0.y);
            ap2[2]=pk2(t0.z,t0.z); ap2[3]=pk2(t0.w,t0.w);
            ap2[4]=pk2(t1.x,t1.x); ap2[5]=pk2(t1.y,t1.y);
            ap2[6]=pk2(t1.z,t1.z); ap2[7]=pk2(t1.w,t1.w);
#pragma unroll
            for (int jh=0;jh<4;jh++)
#pragma unroll
                for (int i=0;i<8;i++)
                    fma2(acc2[i][jh], ap2[i], bp[jh]);
        }
        if (kt + 1 < NKT) {
            const int nb2 = buf^1;
#pragma unroll
            for (int i=0;i<4;i++) As[nb2][a_k+i][a_m] = ar[i];
#pragma unroll
            for (int i=0;i<4;i++) Bs[nb2][w_k+i][w_n] = br[i];
        }
        __syncthreads();
        buf ^= 1;
    }

#pragma unroll
    for (int i=0;i<8;i++){
        const int mr = m0 + ((i<4)? (tm+i) : (64+tm+i-4));
        float* op = g_feat + (size_t)mr*CMID + n0;
#pragma unroll
        for (int jh=0;jh<4;jh++){
            float v0, v1;
            upk2(acc2[i][jh], v0, v1);
            const int j0 = 2*jh, j1 = 2*jh+1;
            const int nc0 = (j0<4)? (tn+j0) : (64+tn+j0-4);
            const int nc1 = (j1<4)? (tn+j1) : (64+tn+j1-4);
            float w0 = v0 + bias[n0+nc0];
            float w1 = v1 + bias[n0+nc1];
            op[nc0] = w0 > 0.f ? w0 : 0.f;
            op[nc1] = w1 > 0.f ? w1 : 0.f;
        }
    }
}

// ---------------------------------------------------------------------------
// 1x1 heads + softmax + anchor decode + clip + histogram.
// 4 pixels per warp-iteration: smem weight traffic /4 vs 1-pixel version.
// ---------------------------------------------------------------------------
__global__ void __launch_bounds__(512)
head_kernel(const float* __restrict__ cls_w, const float* __restrict__ cls_b,
            const float* __restrict__ bbox_w, const float* __restrict__ bbox_b,
            const float* __restrict__ im_info){
    extern __shared__ float ws[];            // 54*512 floats
    __shared__ float bs[54];
    __shared__ float obuf[16][4][54];        // per-warp outputs for 4 pixels
    const int tid = threadIdx.x;
    for (int i = tid; i < 18*512; i += 512) ws[i] = cls_w[i];
    for (int i = tid; i < 36*512; i += 512) ws[18*512 + i] = bbox_w[i];
    if (tid < 18) bs[tid] = cls_b[tid];
    else if (tid < 54) bs[tid] = bbox_b[tid-18];
    __syncthreads();

    const int lane = tid & 31;
    const int warp = tid >> 5;
    const int gw = blockIdx.x*16 + warp;
    const int nw = gridDim.x*16;
    for (int mb = gw*4; mb < MTOT; mb += nw*4) {
        float fr[4][16];
#pragma unroll
        for (int p=0;p<4;p++){
            const float* f = g_feat + (size_t)(mb+p)*CMID;
#pragma unroll
            for (int j=0;j<16;j++) fr[p][j] = f[lane + 32*j];
        }
        for (int t=0;t<54;t++){
            const float* wr = ws + t*512;
            float s0=0.f, s1=0.f, s2=0.f, s3=0.f;
#pragma unroll
            for (int j=0;j<16;j++){
                float wv = wr[lane+32*j];
                s0 += fr[0][j]*wv; s1 += fr[1][j]*wv;
                s2 += fr[2][j]*wv; s3 += fr[3][j]*wv;
            }
#pragma unroll
            for (int d=16; d>0; d>>=1){
                s0 += __shfl_xor_sync(0xffffffffu, s0, d);
                s1 += __shfl_xor_sync(0xffffffffu, s1, d);
                s2 += __shfl_xor_sync(0xffffffffu, s2, d);
                s3 += __shfl_xor_sync(0xffffffffu, s3, d);
            }
            if (lane==0){
                float bv = bs[t];
                obuf[warp][0][t] = s0 + bv;
                obuf[warp][1][t] = s1 + bv;
                obuf[warp][2][t] = s2 + bv;
                obuf[warp][3][t] = s3 + bv;
            }
        }
        __syncwarp();
#pragma unroll
        for (int p=0;p<4;p++){
            if (lane < 9) {
                const float* o = obuf[warp][p];
                const int m = mb + p;
                const int a  = lane;
                const int b  = m >> 12;
                const int yx = m & 4095;
                const int py = yx >> 6, px = yx & 63;
                float c0 = o[a], c1 = o[9+a];
                float mx = fmaxf(c0,c1);
                float e0 = expf(c0-mx), e1 = expf(c1-mx);
                float sc = e1/(e0+e1);
                float dx = o[18+a*4+0], dy = o[18+a*4+1];
                float dw = o[18+a*4+2], dh = o[18+a*4+3];
                float wa = c_wa[a], ha = c_ha[a];
                float cxa = 7.5f + 16.f*(float)px;
                float cya = 7.5f + 16.f*(float)py;
                float cx = dx*wa + cxa;
                float cy = dy*ha + cya;
                float pw = expf(dw)*wa;
                float ph = expf(dh)*ha;
                float imh = im_info[b*3+0], imw = im_info[b*3+1];
                float x1 = fminf(fmaxf(cx - 0.5f*pw, 0.f), imw - 1.f);
                float y1 = fminf(fmaxf(cy - 0.5f*ph, 0.f), imh - 1.f);
                float x2 = fminf(fmaxf(cx + 0.5f*pw, 0.f), imw - 1.f);
                float y2 = fminf(fmaxf(cy + 0.5f*ph, 0.f), imh - 1.f);
                const int idx = yx*9 + a;
                float* bp = g_boxes + ((size_t)b*NANCH + idx)*4;
                bp[0]=x1; bp[1]=y1; bp[2]=x2; bp[3]=y2;
                unsigned bits = __float_as_uint(sc);
                g_sbits[b*NANCH + idx] = bits;
                atomicAdd(&g_hist[b*NBUCKET + (bits>>16)], 1);
            }
        }
        __syncwarp();
    }
}

// ---------------------------------------------------------------------------
// Per-image threshold bucket: smallest T with count(bucket >= T) >= 6000.
// ---------------------------------------------------------------------------
__global__ void __launch_bounds__(1024) thresh_kernel(){
    __shared__ int csum[1024];
    const int b = blockIdx.x;
    const int t = threadIdx.x;
    const int* h = g_hist + b*NBUCKET;
    const int base = t*64;
    int s = 0;
    for (int i=0;i<64;i++) s += h[base+i];
    csum[t] = s;
    __syncthreads();
    for (int d=1; d<1024; d<<=1){               // suffix scan
        int add = (t+d < 1024) ? csum[t+d] : 0;
        __syncthreads();
        csum[t] += add;
        __syncthreads();
    }
    int St = csum[t];
    int Sn = (t+1 < 1024) ? csum[t+1] : 0;
    if (St >= PRE_TOPN && Sn < PRE_TOPN){
        int acc = Sn;
        int T = base;
        for (int i=63;i>=0;i--){
            acc += h[base+i];
            if (acc >= PRE_TOPN){ T = base+i; break; }
        }
        g_thr[b] = T;
    }
}

__global__ void compact_kernel(){
    int i = blockIdx.x*256 + threadIdx.x;
    if (i >= NB*NANCH) return;
    int b = i / NANCH;
    int idx = i - b*NANCH;
    unsigned bits = g_sbits[i];
    if ((int)(bits >> 16) >= g_thr[b]){
        int p = atomicAdd(&g_cnt[b], 1);
        if (p < SEL_CAP)
            g_sel[b*SEL_CAP + p] = ((unsigned long long)bits << 32) | (unsigned)(~idx);
    }
}

// ---------------------------------------------------------------------------
// In-smem bitonic sort of 16384 packed keys per image (descending).
// ---------------------------------------------------------------------------
__global__ void __launch_bounds__(1024) sort_kernel(){
    extern __shared__ unsigned long long sh[];
    const int b = blockIdx.x;
    unsigned long long* gs = g_sel + b*SEL_CAP;
    for (int i=threadIdx.x;i<SEL_CAP;i+=1024) sh[i] = gs[i];
    __syncthreads();
    for (int k=2;k<=SEL_CAP;k<<=1){
        for (int j=k>>1;j>0;j>>=1){
            for (int t=threadIdx.x;t<SEL_CAP/2;t+=1024){
                int i  = 2*t - (t & (j-1));
                int ix = i + j;
                unsigned long long a = sh[i], c = sh[ix];
                bool dir = ((i & k) == 0);        // descending overall
                bool sw  = dir ? (a < c) : (a > c);
                if (sw){ sh[i]=c; sh[ix]=a; }
            }
            __syncthreads();
        }
    }
    for (int i=threadIdx.x;i<SEL_CAP;i+=1024) gs[i]=sh[i];
}

// ---------------------------------------------------------------------------
// Greedy NMS on sorted top-6000.
// ---------------------------------------------------------------------------
__global__ void __launch_bounds__(1024) nms_kernel(float* __restrict__ out){
    extern __shared__ float sm[];
    float* X1 = sm;
    float* Y1 = X1 + PRE_TOPN;
    float* X2 = Y1 + PRE_TOPN;
    float* Y2 = X2 + PRE_TOPN;
    float* AR = Y2 + PRE_TOPN;
    float* SC = AR + PRE_TOPN;
    __shared__ int   s_pick;
    __shared__ float s_box[5];
    const int b = blockIdx.x;
    const unsigned long long* keys = g_sel + b*SEL_CAP;
    for (int i=threadIdx.x;i<PRE_TOPN;i+=1024){
        unsigned long long kv = keys[i];
        unsigned idx = ~(unsigned)(kv & 0xFFFFFFFFull);
        float sc = __uint_as_float((unsigned)(kv >> 32));
        const float* bp = g_boxes + ((size_t)b*NANCH + idx)*4;
        float x1=bp[0], y1=bp[1], x2=bp[2], y2=bp[3];
        X1[i]=x1; Y1[i]=y1; X2[i]=x2; Y2[i]=y2;
        AR[i]=(x2-x1+1.f)*(y2-y1+1.f);
        SC[i]=sc;
    }
    __syncthreads();
    int p = 0;   // only thread 0 uses it
    for (int it=0; it<POST_TOPN; ++it){
        if (threadIdx.x == 0){
            while (p < PRE_TOPN && SC[p] == NEGF) p++;
            if (p < PRE_TOPN){
                s_pick = p;
                s_box[0]=X1[p]; s_box[1]=Y1[p]; s_box[2]=X2[p]; s_box[3]=Y2[p]; s_box[4]=AR[p];
                float* r = out + (size_t)(b*POST_TOPN + it)*5;
                r[0]=(float)b; r[1]=X1[p]; r[2]=Y1[p]; r[3]=X2[p]; r[4]=Y2[p];
                out[NB*POST_TOPN*5 + b*POST_TOPN + it] = SC[p];
            } else {
                s_pick = -1;
                float* r = out + (size_t)(b*POST_TOPN + it)*5;
                r[0]=0.f; r[1]=0.f; r[2]=0.f; r[3]=0.f; r[4]=0.f;
                out[NB*POST_TOPN*5 + b*POST_TOPN + it] = 0.f;
            }
        }
        __syncthreads();
        if (s_pick >= 0){
            float bx1=s_box[0], by1=s_box[1], bx2=s_box[2], by2=s_box[3], ba=s_box[4];
            for (int i=threadIdx.x;i<PRE_TOPN;i+=1024){
                float sc = SC[i];
                if (sc == NEGF) continue;
                float xx1 = fmaxf(bx1, X1[i]);
                float yy1 = fmaxf(by1, Y1[i]);
                float xx2 = fminf(bx2, X2[i]);
                float yy2 = fminf(by2, Y2[i]);
                float iw = fmaxf(xx2-xx1+1.f, 0.f);
                float ih = fmaxf(yy2-yy1+1.f, 0.f);
                float inter = iw*ih;
                float iou = inter/(ba + AR[i] - inter);
                if (iou > 0.7f) SC[i] = NEGF;
            }
        }
        __syncthreads();
    }
}

// ---------------------------------------------------------------------------
extern "C" void kernel_launch(void* const* d_in, const int* in_sizes, int n_in,
                              void* d_out, int out_size) {
    (void)in_sizes; (void)n_in; (void)out_size;
    const float* base_feat = (const float*)d_in[0];
    const float* im_info   = (const float*)d_in[1];
    const float* conv_w    = (const float*)d_in[4];
    const float* conv_b    = (const float*)d_in[5];
    const float* cls_w     = (const float*)d_in[6];
    const float* cls_b     = (const float*)d_in[7];
    const float* bbox_w    = (const float*)d_in[8];
    const float* bbox_b    = (const float*)d_in[9];
    float* out = (float*)d_out;

    cudaFuncSetAttribute(head_kernel, cudaFuncAttributeMaxDynamicSharedMemorySize, 54*512*4);
    cudaFuncSetAttribute(sort_kernel, cudaFuncAttributeMaxDynamicSharedMemorySize, SEL_CAP*8);
    cudaFuncSetAttribute(nms_kernel,  cudaFuncAttributeMaxDynamicSharedMemorySize, PRE_TOPN*6*4);

    transpose_w_kernel<<<dim3(128,4), 256>>>(conv_w);
    init_kernel<<<(NB*NBUCKET + 255)/256, 256>>>();
    conv3x3_kernel<<<dim3(4,128), 256>>>(base_feat, conv_b);
    head_kernel<<<148, 512, 54*512*4>>>(cls_w, cls_b, bbox_w, bbox_b, im_info);
    thresh_kernel<<<NB, 1024>>>();
    compact_kernel<<<(NB*NANCH + 255)/256, 256>>>();
    sort_kernel<<<NB, 1024, SEL_CAP*8>>>();
    nms_kernel<<<NB, 1024, PRE_TOPN*6*4>>>(out);
}